// round 1
// baseline (speedup 1.0000x reference)
#include <cuda_runtime.h>

// Tucker contraction: y[n] = sum_{p,q,r} U[i_n,p] * V[j_n,q] * T[k_n,r] * C[p,q,r]
// P=Q=R=32, N=131072.
//
// Strategy (round 1 baseline):
//  - Core tensor C (128KB) staged in shared memory once per CTA, rows (p,q)
//    padded to stride 36 floats -> conflict-free LDS.128 across lanes (lane=q).
//  - One warp processes S=4 samples at a time (amortizes C reads 4x).
//  - lane owns q. acc_q[s] = sum_p u_s[p] * (sum_r t_s[r] * C[p,q,r])
//    inner sum over r vectorized float4.
//  - final: y = warp-reduce over q of acc_q * v_q.
//  - persistent grid of 148 CTAs x 1024 threads (32 warps), grid-stride over
//    sample groups.

#define WARPS_PER_CTA 32
#define CTA_THREADS   (WARPS_PER_CTA * 32)
#define NUM_CTAS      148
#define ROW_STRIDE    36   // 32 floats + 4 pad: (36*l + r) % 32 = (4l+r)%32, distinct per 8-lane phase

// shared memory layout (floats):
//   Cs      : 1024 rows * 36               = 36864 floats (147456 B)
//   u_stage : WARPS * 32(p) * 4(s)         = 4096 floats  (16384 B)
//   t_stage : WARPS * 4(s) * 32(r)         = 4096 floats  (16384 B)
#define SMEM_FLOATS (1024 * ROW_STRIDE + WARPS_PER_CTA * 128 + WARPS_PER_CTA * 128)

__global__ void __launch_bounds__(CTA_THREADS, 1)
tucker_kernel(const int* __restrict__ i_in,
              const int* __restrict__ j_in,
              const int* __restrict__ k_in,
              const float* __restrict__ U,
              const float* __restrict__ V,
              const float* __restrict__ T,
              const float* __restrict__ C,
              float* __restrict__ out,
              int n)
{
    extern __shared__ float sm[];
    float* Cs     = sm;                              // 1024*36
    float* u_base = sm + 1024 * ROW_STRIDE;          // [warp][p][s]
    float* t_base = u_base + WARPS_PER_CTA * 128;    // [warp][s][r]

    const int tid = threadIdx.x;

    // Stage core tensor: C[p][q][r] -> Cs[(p*32+q)*36 + r]
    for (int idx = tid; idx < 32768; idx += CTA_THREADS) {
        int row = idx >> 5;       // p*32+q
        int col = idx & 31;       // r
        Cs[row * ROW_STRIDE + col] = C[idx];
    }
    __syncthreads();

    const int w    = tid >> 5;
    const int lane = tid & 31;
    float* uw = u_base + w * 128;   // uw[p*4 + s]
    float* tw = t_base + w * 128;   // tw[s*32 + r]

    const int ngroups = n >> 2;                         // 4 samples per group
    const int gstride = gridDim.x * WARPS_PER_CTA;

    for (int g = blockIdx.x * WARPS_PER_CTA + w; g < ngroups; g += gstride) {
        const int base = g << 2;

        // Stage u (layout [p][s]) and t (layout [s][r]) for 4 samples.
        float acc0 = 0.f, acc1 = 0.f, acc2 = 0.f, acc3 = 0.f;
        #pragma unroll
        for (int s = 0; s < 4; s++) {
            int iu = i_in[base + s];
            int ik = k_in[base + s];
            uw[lane * 4 + s] = U[iu * 32 + lane];
            tw[s * 32 + lane] = T[ik * 32 + lane];
        }
        __syncwarp();

        const float4* cw = (const float4*)(Cs + lane * ROW_STRIDE);
        #pragma unroll 1
        for (int p = 0; p < 32; p++) {
            // broadcast u[p] for the 4 samples in one 16B load
            float4 up = *(const float4*)(uw + p * 4);
            float in0 = 0.f, in1 = 0.f, in2 = 0.f, in3 = 0.f;
            const float4* crow = cw + p * (32 * ROW_STRIDE / 4);
            #pragma unroll
            for (int r4 = 0; r4 < 8; r4++) {
                float4 c = crow[r4];   // Cs[p][lane][4*r4 .. +3], conflict-free
                float4 t0 = *(const float4*)(tw +  0 + r4 * 4);
                float4 t1 = *(const float4*)(tw + 32 + r4 * 4);
                float4 t2 = *(const float4*)(tw + 64 + r4 * 4);
                float4 t3 = *(const float4*)(tw + 96 + r4 * 4);
                in0 = fmaf(c.x, t0.x, in0); in0 = fmaf(c.y, t0.y, in0);
                in0 = fmaf(c.z, t0.z, in0); in0 = fmaf(c.w, t0.w, in0);
                in1 = fmaf(c.x, t1.x, in1); in1 = fmaf(c.y, t1.y, in1);
                in1 = fmaf(c.z, t1.z, in1); in1 = fmaf(c.w, t1.w, in1);
                in2 = fmaf(c.x, t2.x, in2); in2 = fmaf(c.y, t2.y, in2);
                in2 = fmaf(c.z, t2.z, in2); in2 = fmaf(c.w, t2.w, in2);
                in3 = fmaf(c.x, t3.x, in3); in3 = fmaf(c.y, t3.y, in3);
                in3 = fmaf(c.z, t3.z, in3); in3 = fmaf(c.w, t3.w, in3);
            }
            acc0 = fmaf(up.x, in0, acc0);
            acc1 = fmaf(up.y, in1, acc1);
            acc2 = fmaf(up.z, in2, acc2);
            acc3 = fmaf(up.w, in3, acc3);
        }

        // y_s = sum_q acc_s[q] * v_s[q]
        float res[4];
        #pragma unroll
        for (int s = 0; s < 4; s++) {
            int ij = j_in[base + s];
            float v = V[ij * 32 + lane];
            float val = (s == 0 ? acc0 : s == 1 ? acc1 : s == 2 ? acc2 : acc3) * v;
            #pragma unroll
            for (int off = 16; off > 0; off >>= 1)
                val += __shfl_xor_sync(0xffffffffu, val, off);
            res[s] = val;
        }
        if (lane < 4) {
            float o = (lane == 0) ? res[0] : (lane == 1) ? res[1]
                    : (lane == 2) ? res[2] : res[3];
            out[base + lane] = o;
        }
        __syncwarp();   // protect uw/tw before next iteration's staging
    }
}

extern "C" void kernel_launch(void* const* d_in, const int* in_sizes, int n_in,
                              void* d_out, int out_size)
{
    const int*   i_in = (const int*)d_in[0];
    const int*   j_in = (const int*)d_in[1];
    const int*   k_in = (const int*)d_in[2];
    const float* U    = (const float*)d_in[3];
    const float* V    = (const float*)d_in[4];
    const float* T    = (const float*)d_in[5];
    const float* C    = (const float*)d_in[6];
    float*       out  = (float*)d_out;

    const int n = in_sizes[0];
    const size_t smem_bytes = SMEM_FLOATS * sizeof(float);

    static bool configured = false;
    if (!configured) {
        cudaFuncSetAttribute(tucker_kernel,
                             cudaFuncAttributeMaxDynamicSharedMemorySize,
                             (int)smem_bytes);
        configured = true;
    }

    tucker_kernel<<<NUM_CTAS, CTA_THREADS, smem_bytes>>>(
        i_in, j_in, k_in, U, V, T, C, out, n);
}

// round 3
// speedup vs baseline: 10.6931x; 10.6931x over previous
#include <cuda_runtime.h>
#include <cstdint>

// Tucker via time-bucketing:
//   y_n = u_n^T W_{k_n} v_n,   W_k[p,q] = sum_r C[p,q,r] * t_k[r]
// NUM_TIME=5000 << N=131072 -> each W_k amortized over ~26 samples.
// Counting sort by time index, then warp-per-bucket persistent kernel.

#define NTIME       5000
#define MAXN        131072
#define NUM_CTAS    148
#define WARPS       32
#define CTA_THREADS (WARPS * 32)

// ---- device scratch (alloc-free rule: __device__ globals) ----
__device__ int g_counts[NTIME];
__device__ int g_offsets[NTIME + 1];
__device__ int g_cursor[NTIME];
__device__ int g_perm[MAXN];

__global__ void zero_counts_kernel() {
    int t = blockIdx.x * blockDim.x + threadIdx.x;
    if (t < NTIME) g_counts[t] = 0;
}

__global__ void hist_kernel(const int* __restrict__ k_in, int n) {
    int t = blockIdx.x * blockDim.x + threadIdx.x;
    if (t < n) atomicAdd(&g_counts[k_in[t]], 1);
}

// single-CTA exclusive scan over 5000 counts (1024 threads x 5 elems)
__global__ void scan_kernel() {
    __shared__ int part[1024];
    const int t = threadIdx.x;
    const int base = t * 5;
    int local[5];
    int s = 0;
    #pragma unroll
    for (int x = 0; x < 5; x++) {
        int c = (base + x < NTIME) ? g_counts[base + x] : 0;
        local[x] = s;
        s += c;
    }
    part[t] = s;
    __syncthreads();
    #pragma unroll
    for (int off = 1; off < 1024; off <<= 1) {
        int v = (t >= off) ? part[t - off] : 0;
        __syncthreads();
        part[t] += v;
        __syncthreads();
    }
    const int pre = (t == 0) ? 0 : part[t - 1];
    #pragma unroll
    for (int x = 0; x < 5; x++) {
        if (base + x < NTIME) {
            g_offsets[base + x] = pre + local[x];
            g_cursor[base + x]  = pre + local[x];
        }
    }
    if (t == 1023) g_offsets[NTIME] = part[1023];
}

__global__ void scatter_kernel(const int* __restrict__ k_in, int n) {
    int t = blockIdx.x * blockDim.x + threadIdx.x;
    if (t < n) {
        int pos = atomicAdd(&g_cursor[k_in[t]], 1);
        if (pos < MAXN) g_perm[pos] = t;
    }
}

// ---- main kernel ----
// SMEM:
//   Cs2: 32768 floats, layout float4-index (r4*32 + p)*32 + q   (lane=q reads
//        contiguous 16B -> conflict-free LDS.128, p-major inner loop)
//   u_stage: WARPS x 32 floats,  t_stage: WARPS x 32 floats
#define SM_C_FLOATS 32768
#define SM_U_OFF    SM_C_FLOATS
#define SM_T_OFF    (SM_U_OFF + WARPS * 32)
#define SMEM_FLOATS (SM_T_OFF + WARPS * 32)

__global__ void __launch_bounds__(CTA_THREADS, 1)
tucker_main(const int* __restrict__ i_in, const int* __restrict__ j_in,
            const float* __restrict__ U, const float* __restrict__ V,
            const float* __restrict__ T, const float* __restrict__ C,
            float* __restrict__ out)
{
    extern __shared__ float sm[];
    const int tid  = threadIdx.x;
    const int wid  = tid >> 5;
    const int lane = tid & 31;

    // stage C: C[p][q][r] (r contiguous) -> Cs2[((r>>2)*32 + p)*32 + q] float4s
    for (int idx = tid; idx < 32768; idx += CTA_THREADS) {
        int p = idx >> 10, q = (idx >> 5) & 31, r = idx & 31;
        int r4 = r >> 2, rr = r & 3;
        sm[(((r4 * 32 + p) * 32 + q) << 2) + rr] = C[idx];
    }
    __syncthreads();

    float* uws = sm + SM_U_OFF + wid * 32;
    float* tws = sm + SM_T_OFF + wid * 32;
    const float4* tws4 = (const float4*)tws;
    const float4* uws4 = (const float4*)uws;

    const int gwarp   = blockIdx.x * WARPS + wid;
    const int nwarps  = gridDim.x * WARPS;

    for (int b = gwarp; b < NTIME; b += nwarps) {
        const int s0 = g_offsets[b];
        const int s1 = g_offsets[b + 1];
        if (s0 == s1) continue;

        // stage t_b row
        tws[lane] = T[(size_t)b * 32 + lane];
        __syncwarp();

        // W build: w[p] (lane = q) = sum_r C[p][lane][r] * t[r]
        float w[32];
        #pragma unroll
        for (int p = 0; p < 32; p++) w[p] = 0.f;

        #pragma unroll 1
        for (int r4 = 0; r4 < 8; r4++) {
            const float4 t4 = tws4[r4];
            const float4* crow = ((const float4*)sm) + r4 * 1024 + lane;
            #pragma unroll
            for (int p = 0; p < 32; p++) {
                float4 c = crow[p * 32];
                w[p] = fmaf(c.x, t4.x, w[p]);
                w[p] = fmaf(c.y, t4.y, w[p]);
                w[p] = fmaf(c.z, t4.z, w[p]);
                w[p] = fmaf(c.w, t4.w, w[p]);
            }
        }

        // samples in this bucket
        for (int s = s0; s < s1; s++) {
            const int idx = g_perm[s];
            const int iu = i_in[idx];
            const int ij = j_in[idx];

            uws[lane] = U[(size_t)iu * 32 + lane];
            __syncwarp();

            float a = 0.f;
            #pragma unroll
            for (int p4 = 0; p4 < 8; p4++) {
                float4 u4 = uws4[p4];
                a = fmaf(u4.x, w[4 * p4 + 0], a);
                a = fmaf(u4.y, w[4 * p4 + 1], a);
                a = fmaf(u4.z, w[4 * p4 + 2], a);
                a = fmaf(u4.w, w[4 * p4 + 3], a);
            }

            float val = a * V[(size_t)ij * 32 + lane];
            #pragma unroll
            for (int off = 16; off > 0; off >>= 1)
                val += __shfl_xor_sync(0xffffffffu, val, off);
            if (lane == 0) out[idx] = val;
            __syncwarp();   // protect uws before next sample's store
        }
    }
}

extern "C" void kernel_launch(void* const* d_in, const int* in_sizes, int n_in,
                              void* d_out, int out_size)
{
    const int*   i_in = (const int*)d_in[0];
    const int*   j_in = (const int*)d_in[1];
    const int*   k_in = (const int*)d_in[2];
    const float* U    = (const float*)d_in[3];
    const float* V    = (const float*)d_in[4];
    const float* T    = (const float*)d_in[5];
    const float* C    = (const float*)d_in[6];
    float*       out  = (float*)d_out;

    const int n = in_sizes[0];
    const size_t smem_bytes = SMEM_FLOATS * sizeof(float);

    static bool configured = false;
    if (!configured) {
        cudaFuncSetAttribute(tucker_main,
                             cudaFuncAttributeMaxDynamicSharedMemorySize,
                             (int)smem_bytes);
        configured = true;
    }

    zero_counts_kernel<<<(NTIME + 255) / 256, 256>>>();
    hist_kernel<<<(n + 255) / 256, 256>>>(k_in, n);
    scan_kernel<<<1, 1024>>>();
    scatter_kernel<<<(n + 255) / 256, 256>>>(k_in, n);
    tucker_main<<<NUM_CTAS, CTA_THREADS, smem_bytes>>>(i_in, j_in, U, V, T, C, out);
}

// round 5
// speedup vs baseline: 12.3089x; 1.1511x over previous
#include <cuda_runtime.h>
#include <cstdint>

// Tucker via time-bucketing:
//   y_n = u_n^T W_{k_n} v_n,   W_k[p,q] = sum_r C[p,q,r] * t_k[r]
// Counting sort by time index; main kernel: dynamic warp-tasks of 2 buckets
// (shared C reads), batched sample loop.

#define NTIME       5000
#define NTASKS      (NTIME / 2)
#define NUM_CTAS    148
#define CTA_THREADS 512
#define WARPS       (CTA_THREADS / 32)

// ---- device scratch ----
__device__ int g_counts[NTIME];
__device__ int g_offsets[NTIME + 1];
__device__ int g_cursor[NTIME];
__device__ int g_perm[131072 + 4];
__device__ int g_ticket;

__global__ void zero_counts_kernel() {
    int t = blockIdx.x * blockDim.x + threadIdx.x;
    if (t < NTIME) g_counts[t] = 0;
    if (t == 0) g_ticket = 0;
}

__global__ void hist_kernel(const int* __restrict__ k_in, int n) {
    int t = blockIdx.x * blockDim.x + threadIdx.x;
    int base = t * 4;
    if (base + 3 < n) {
        int4 k4 = *(const int4*)(k_in + base);
        atomicAdd(&g_counts[k4.x], 1);
        atomicAdd(&g_counts[k4.y], 1);
        atomicAdd(&g_counts[k4.z], 1);
        atomicAdd(&g_counts[k4.w], 1);
    } else {
        for (int x = base; x < n; x++) atomicAdd(&g_counts[k_in[x]], 1);
    }
}

// single-CTA exclusive scan over 5000 counts
__global__ void scan_kernel() {
    __shared__ int part[1024];
    const int t = threadIdx.x;
    const int base = t * 5;
    int local[5];
    int s = 0;
    #pragma unroll
    for (int x = 0; x < 5; x++) {
        int c = (base + x < NTIME) ? g_counts[base + x] : 0;
        local[x] = s;
        s += c;
    }
    part[t] = s;
    __syncthreads();
    #pragma unroll
    for (int off = 1; off < 1024; off <<= 1) {
        int v = (t >= off) ? part[t - off] : 0;
        __syncthreads();
        part[t] += v;
        __syncthreads();
    }
    const int pre = (t == 0) ? 0 : part[t - 1];
    #pragma unroll
    for (int x = 0; x < 5; x++) {
        if (base + x < NTIME) {
            g_offsets[base + x] = pre + local[x];
            g_cursor[base + x]  = pre + local[x];
        }
    }
    if (t == 1023) g_offsets[NTIME] = part[1023];
}

__global__ void scatter_kernel(const int* __restrict__ k_in, int n) {
    int t = blockIdx.x * blockDim.x + threadIdx.x;
    int base = t * 4;
    if (base + 3 < n) {
        int4 k4 = *(const int4*)(k_in + base);
        int p0 = atomicAdd(&g_cursor[k4.x], 1);
        int p1 = atomicAdd(&g_cursor[k4.y], 1);
        int p2 = atomicAdd(&g_cursor[k4.z], 1);
        int p3 = atomicAdd(&g_cursor[k4.w], 1);
        g_perm[p0] = base; g_perm[p1] = base + 1;
        g_perm[p2] = base + 2; g_perm[p3] = base + 3;
    } else {
        for (int x = base; x < n; x++) {
            int pos = atomicAdd(&g_cursor[k_in[x]], 1);
            g_perm[pos] = x;
        }
    }
}

// ---- main kernel ----
// SMEM: C 32768 floats laid out float4-index (r4*32 + p)*32 + q  (lane=q,
//       16B/lane contiguous -> conflict-free LDS.128), then per-warp t (2x32)
//       and u (4x32) staging.
#define SM_T_OFF (32768)
#define SM_U_OFF (SM_T_OFF + WARPS * 64)
#define SMEM_FLOATS (SM_U_OFF + WARPS * 128)

__device__ __forceinline__ void process_bucket(
    const float* __restrict__ w,     // w[32] in regs (unrolled constant indexing)
    float* uws, int b,
    const int* __restrict__ i_in, const int* __restrict__ j_in,
    const float* __restrict__ U, const float* __restrict__ V,
    float* __restrict__ out, int lane)
{
    const int s0 = g_offsets[b];
    const int s1 = g_offsets[b + 1];
    const float4* uws4 = (const float4*)uws;

    for (int base = s0; base < s1; base += 32) {
        const int cnt = min(32, s1 - base);
        const int my = base + min(lane, cnt - 1);
        const int idx_l = g_perm[my];
        const int iu_l  = i_in[idx_l];
        const int ij_l  = j_in[idx_l];

        for (int so = 0; so < cnt; so += 4) {
            const int nb = min(4, cnt - so);
            #pragma unroll
            for (int s = 0; s < 4; s++) {
                if (s < nb) {
                    int iu = __shfl_sync(0xffffffffu, iu_l, so + s);
                    uws[s * 32 + lane] = U[(size_t)iu * 32 + lane];
                }
            }
            __syncwarp();
            #pragma unroll
            for (int s = 0; s < 4; s++) {
                if (s < nb) {
                    // warp-uniform broadcasts (ALL lanes execute every shfl)
                    int ij  = __shfl_sync(0xffffffffu, ij_l,  so + s);
                    int idx = __shfl_sync(0xffffffffu, idx_l, so + s);
                    float v = V[(size_t)ij * 32 + lane];
                    float a = 0.f;
                    #pragma unroll
                    for (int p4 = 0; p4 < 8; p4++) {
                        float4 u4 = uws4[s * 8 + p4];     // broadcast
                        a = fmaf(u4.x, w[4 * p4 + 0], a);
                        a = fmaf(u4.y, w[4 * p4 + 1], a);
                        a = fmaf(u4.z, w[4 * p4 + 2], a);
                        a = fmaf(u4.w, w[4 * p4 + 3], a);
                    }
                    float val = a * v;
                    #pragma unroll
                    for (int off = 16; off > 0; off >>= 1)
                        val += __shfl_xor_sync(0xffffffffu, val, off);
                    if (lane == 0) out[idx] = val;
                }
            }
            __syncwarp();
        }
    }
}

__global__ void __launch_bounds__(CTA_THREADS, 1)
tucker_main(const int* __restrict__ i_in, const int* __restrict__ j_in,
            const float* __restrict__ U, const float* __restrict__ V,
            const float* __restrict__ T, const float* __restrict__ C,
            float* __restrict__ out)
{
    extern __shared__ float sm[];
    const int tid  = threadIdx.x;
    const int wid  = tid >> 5;
    const int lane = tid & 31;

    // stage C (vectorized): C[p][q][r] -> sm4[(r4*32+p)*32 + q]
    {
        const float4* C4 = (const float4*)C;
        float4* sm4 = (float4*)sm;
        for (int idx = tid; idx < 8192; idx += CTA_THREADS) {
            int p = idx >> 8, q = (idx >> 3) & 31, r4 = idx & 7;
            sm4[(r4 * 32 + p) * 32 + q] = C4[idx];
        }
    }
    __syncthreads();

    float* tws = sm + SM_T_OFF + wid * 64;
    float* uws = sm + SM_U_OFF + wid * 128;
    const float4* tws4 = (const float4*)tws;

    while (true) {
        int task;
        if (lane == 0) task = atomicAdd(&g_ticket, 1);
        task = __shfl_sync(0xffffffffu, task, 0);
        if (task >= NTASKS) break;

        const int b0 = task * 2;
        tws[lane]      = T[(size_t)b0 * 32 + lane];
        tws[32 + lane] = T[(size_t)(b0 + 1) * 32 + lane];
        __syncwarp();

        float w0[32], w1[32];
        #pragma unroll
        for (int p = 0; p < 32; p++) { w0[p] = 0.f; w1[p] = 0.f; }

        #pragma unroll 1
        for (int r4 = 0; r4 < 8; r4++) {
            const float4 ta = tws4[r4];
            const float4 tb = tws4[8 + r4];
            const float4* crow = ((const float4*)sm) + r4 * 1024 + lane;
            #pragma unroll
            for (int p = 0; p < 32; p++) {
                float4 c = crow[p * 32];
                w0[p] = fmaf(c.x, ta.x, w0[p]); w1[p] = fmaf(c.x, tb.x, w1[p]);
                w0[p] = fmaf(c.y, ta.y, w0[p]); w1[p] = fmaf(c.y, tb.y, w1[p]);
                w0[p] = fmaf(c.z, ta.z, w0[p]); w1[p] = fmaf(c.z, tb.z, w1[p]);
                w0[p] = fmaf(c.w, ta.w, w0[p]); w1[p] = fmaf(c.w, tb.w, w1[p]);
            }
        }

        process_bucket(w0, uws, b0,     i_in, j_in, U, V, out, lane);
        process_bucket(w1, uws, b0 + 1, i_in, j_in, U, V, out, lane);
    }
}

extern "C" void kernel_launch(void* const* d_in, const int* in_sizes, int n_in,
                              void* d_out, int out_size)
{
    const int*   i_in = (const int*)d_in[0];
    const int*   j_in = (const int*)d_in[1];
    const int*   k_in = (const int*)d_in[2];
    const float* U    = (const float*)d_in[3];
    const float* V    = (const float*)d_in[4];
    const float* T    = (const float*)d_in[5];
    const float* C    = (const float*)d_in[6];
    float*       out  = (float*)d_out;

    const int n = in_sizes[0];
    const size_t smem_bytes = SMEM_FLOATS * sizeof(float);

    static bool configured = false;
    if (!configured) {
        cudaFuncSetAttribute(tucker_main,
                             cudaFuncAttributeMaxDynamicSharedMemorySize,
                             (int)smem_bytes);
        configured = true;
    }

    const int q4 = (n + 3) / 4;
    zero_counts_kernel<<<(NTIME + 255) / 256, 256>>>();
    hist_kernel<<<(q4 + 255) / 256, 256>>>(k_in, n);
    scan_kernel<<<1, 1024>>>();
    scatter_kernel<<<(q4 + 255) / 256, 256>>>(k_in, n);
    tucker_main<<<NUM_CTAS, CTA_THREADS, smem_bytes>>>(i_in, j_in, U, V, T, C, out);
}

// round 6
// speedup vs baseline: 13.3276x; 1.0828x over previous
#include <cuda_runtime.h>
#include <cstdint>

// Tucker via time-bucketing, round 6:
//   y_n = u_n^T W_{k_n} v_n,   W_k[p,q] = sum_r C[p,q,r] * t_k[r]
// - counting sort by k; scatter also pre-gathers i/j into sorted order
// - main: warp-task = 2 buckets (shared C reads), W built in packed f32x2
//   regs, stored to per-warp SMEM; sample phase lane=sample (no shfl/sync)

#define NTIME       5000
#define NTASKS      (NTIME / 2)
#define NUM_CTAS    148
#define CTA_THREADS 384
#define WARPS       (CTA_THREADS / 32)
#define MAXN        131072

// ---- device scratch ----
__device__ int g_counts[NTIME];
__device__ int g_offsets[NTIME + 1];
__device__ int g_cursor[NTIME];
__device__ int g_perm[MAXN];
__device__ int g_si[MAXN];
__device__ int g_sj[MAXN];
__device__ int g_ticket;

__global__ void zero_counts_kernel() {
    int t = blockIdx.x * blockDim.x + threadIdx.x;
    if (t < NTIME) g_counts[t] = 0;
    if (t == 0) g_ticket = 0;
}

__global__ void hist_kernel(const int* __restrict__ k_in, int n) {
    int t = blockIdx.x * blockDim.x + threadIdx.x;
    int base = t * 4;
    if (base + 3 < n) {
        int4 k4 = *(const int4*)(k_in + base);
        atomicAdd(&g_counts[k4.x], 1);
        atomicAdd(&g_counts[k4.y], 1);
        atomicAdd(&g_counts[k4.z], 1);
        atomicAdd(&g_counts[k4.w], 1);
    } else {
        for (int x = base; x < n; x++) atomicAdd(&g_counts[k_in[x]], 1);
    }
}

__global__ void scan_kernel() {
    __shared__ int part[1024];
    const int t = threadIdx.x;
    const int base = t * 5;
    int local[5];
    int s = 0;
    #pragma unroll
    for (int x = 0; x < 5; x++) {
        int c = (base + x < NTIME) ? g_counts[base + x] : 0;
        local[x] = s;
        s += c;
    }
    part[t] = s;
    __syncthreads();
    #pragma unroll
    for (int off = 1; off < 1024; off <<= 1) {
        int v = (t >= off) ? part[t - off] : 0;
        __syncthreads();
        part[t] += v;
        __syncthreads();
    }
    const int pre = (t == 0) ? 0 : part[t - 1];
    #pragma unroll
    for (int x = 0; x < 5; x++) {
        if (base + x < NTIME) {
            g_offsets[base + x] = pre + local[x];
            g_cursor[base + x]  = pre + local[x];
        }
    }
    if (t == 1023) g_offsets[NTIME] = part[1023];
}

// scatter + pre-gather i/j into sorted order
__global__ void scatter_kernel(const int* __restrict__ k_in,
                               const int* __restrict__ i_in,
                               const int* __restrict__ j_in, int n) {
    int x = blockIdx.x * blockDim.x + threadIdx.x;
    if (x < n) {
        int k  = k_in[x];
        int iu = i_in[x];
        int ij = j_in[x];
        int pos = atomicAdd(&g_cursor[k], 1);
        g_perm[pos] = x;
        g_si[pos]   = iu;
        g_sj[pos]   = ij;
    }
}

// ---- packed f32x2 helpers ----
#define PACK2(d, lo, hi) asm("mov.b64 %0, {%1, %2};" : "=l"(d) : "f"(lo), "f"(hi))
#define UNPACK2(lo, hi, s) asm("mov.b64 {%0, %1}, %2;" : "=f"(lo), "=f"(hi) : "l"(s))
#define FMA2(acc, a, b) asm("fma.rn.f32x2 %0, %1, %2, %0;" : "+l"(acc) : "l"(a), "l"(b))
#define LDS64(d, addr) asm volatile("ld.shared.b64 %0, [%1];" : "=l"(d) : "r"(addr))
#define LDSV2U64(d0, d1, addr) \
    asm volatile("ld.shared.v2.u64 {%0, %1}, [%2];" : "=l"(d0), "=l"(d1) : "r"(addr))

__device__ __forceinline__ uint32_t smem_u32(const void* p) {
    uint32_t a;
    asm("{ .reg .u64 t; cvta.to.shared.u64 t, %1; cvt.u32.u64 %0, t; }" : "=r"(a) : "l"(p));
    return a;
}

// ---- main kernel ----
// SMEM bytes:
//   [0, 131072)            C packed: float2(C[2p2][q][r], C[2p2+1][q][r]) at
//                          byte r*4096 + p2*256 + q*8
//   [131072, 131072+W*8K)  per-warp W0 (4KB) + W1 (4KB), row-major [p][q]
#define SM_C_BYTES 131072
#define SMEM_BYTES (SM_C_BYTES + WARPS * 8192)

__device__ __forceinline__ void process_bucket(
    uint32_t Waddr, int s0, int s1,
    const float* __restrict__ U, const float* __restrict__ V,
    float* __restrict__ out, int lane)
{
    for (int base = s0; base < s1; base += 32) {
        const int cnt = s1 - base;                 // >0
        const int pos = base + min(lane, cnt - 1);
        const int iu  = g_si[pos];
        const int ij  = g_sj[pos];
        const int idx = g_perm[pos];

        // load u row and v row into registers (16 LDG.128 in flight)
        float ua[32], va[32];
        {
            const float4* up = (const float4*)(U + (size_t)iu * 32);
            const float4* vp = (const float4*)(V + (size_t)ij * 32);
            #pragma unroll
            for (int x = 0; x < 8; x++) {
                float4 t = up[x];
                ua[4*x] = t.x; ua[4*x+1] = t.y; ua[4*x+2] = t.z; ua[4*x+3] = t.w;
            }
            #pragma unroll
            for (int x = 0; x < 8; x++) {
                float4 t = vp[x];
                va[4*x] = t.x; va[4*x+1] = t.y; va[4*x+2] = t.z; va[4*x+3] = t.w;
            }
        }

        // a[q] = sum_p u_p * W[p][q], packed over q-pairs
        unsigned long long a2[16];
        #pragma unroll
        for (int x = 0; x < 16; x++) a2[x] = 0ULL;

        #pragma unroll 8
        for (int p = 0; p < 32; p++) {
            unsigned long long upk;
            PACK2(upk, ua[p], ua[p]);
            const uint32_t row = Waddr + (uint32_t)p * 128u;   // uniform -> broadcast
            #pragma unroll
            for (int q4 = 0; q4 < 8; q4++) {
                unsigned long long c0, c1;
                LDSV2U64(c0, c1, row + q4 * 16u);
                FMA2(a2[2*q4],     upk, c0);
                FMA2(a2[2*q4 + 1], upk, c1);
            }
        }

        // y = sum_q a_q * v_q
        unsigned long long acc2 = 0ULL;
        #pragma unroll
        for (int q2 = 0; q2 < 16; q2++) {
            unsigned long long v2;
            PACK2(v2, va[2*q2], va[2*q2+1]);
            FMA2(acc2, a2[q2], v2);
        }
        float ylo, yhi;
        UNPACK2(ylo, yhi, acc2);
        if (lane < cnt) out[idx] = ylo + yhi;
    }
}

__global__ void __launch_bounds__(CTA_THREADS, 1)
tucker_main(const float* __restrict__ U, const float* __restrict__ V,
            const float* __restrict__ T, const float* __restrict__ C,
            float* __restrict__ out)
{
    extern __shared__ float sm[];
    const uint32_t smb = smem_u32(sm);
    const int tid  = threadIdx.x;
    const int wid  = tid >> 5;
    const int lane = tid & 31;

    // stage C: C[p][q][r] -> packed float2 over p-pairs
    for (int idx = tid; idx < 32768; idx += CTA_THREADS) {
        int p = idx >> 10, q = (idx >> 5) & 31, r = idx & 31;
        sm[((r * 16 + (p >> 1)) * 32 + q) * 2 + (p & 1)] = C[idx];
    }
    __syncthreads();

    const uint32_t W0addr = smb + SM_C_BYTES + (uint32_t)wid * 8192u;
    const uint32_t W1addr = W0addr + 4096u;
    float* W0f = (float*)(sm) + (SM_C_BYTES / 4) + wid * 2048;
    float* W1f = W0f + 1024;

    while (true) {
        int task;
        if (lane == 0) task = atomicAdd(&g_ticket, 1);
        task = __shfl_sync(0xffffffffu, task, 0);
        if (task >= NTASKS) break;

        const int b0 = task * 2;
        const float t0v = T[(size_t)b0 * 32 + lane];
        const float t1v = T[(size_t)(b0 + 1) * 32 + lane];

        // W build, packed over p-pairs: w[p2] lo=p even, hi=p odd
        unsigned long long w0[16], w1[16];
        #pragma unroll
        for (int x = 0; x < 16; x++) { w0[x] = 0ULL; w1[x] = 0ULL; }

        #pragma unroll 4
        for (int r = 0; r < 32; r++) {
            float f0 = __shfl_sync(0xffffffffu, t0v, r);
            float f1 = __shfl_sync(0xffffffffu, t1v, r);
            unsigned long long tr0, tr1;
            PACK2(tr0, f0, f0);
            PACK2(tr1, f1, f1);
            const uint32_t ra = smb + (uint32_t)r * 4096u + (uint32_t)lane * 8u;
            #pragma unroll
            for (int p2 = 0; p2 < 16; p2++) {
                unsigned long long c2;
                LDS64(c2, ra + p2 * 256u);
                FMA2(w0[p2], c2, tr0);
                FMA2(w1[p2], c2, tr1);
            }
        }

        // store W to per-warp SMEM, row-major [p][q], lane=q (conflict-free)
        #pragma unroll
        for (int p2 = 0; p2 < 16; p2++) {
            float a, b;
            UNPACK2(a, b, w0[p2]);
            W0f[(2*p2) * 32 + lane]     = a;
            W0f[(2*p2 + 1) * 32 + lane] = b;
            UNPACK2(a, b, w1[p2]);
            W1f[(2*p2) * 32 + lane]     = a;
            W1f[(2*p2 + 1) * 32 + lane] = b;
        }
        __syncwarp();

        const int s00 = g_offsets[b0];
        const int s01 = g_offsets[b0 + 1];
        const int s11 = g_offsets[b0 + 2];
        process_bucket(W0addr, s00, s01, U, V, out, lane);
        process_bucket(W1addr, s01, s11, U, V, out, lane);
        __syncwarp();   // W smem reused next task
    }
}

extern "C" void kernel_launch(void* const* d_in, const int* in_sizes, int n_in,
                              void* d_out, int out_size)
{
    const int*   i_in = (const int*)d_in[0];
    const int*   j_in = (const int*)d_in[1];
    const int*   k_in = (const int*)d_in[2];
    const float* U    = (const float*)d_in[3];
    const float* V    = (const float*)d_in[4];
    const float* T    = (const float*)d_in[5];
    const float* C    = (const float*)d_in[6];
    float*       out  = (float*)d_out;

    const int n = in_sizes[0];

    static bool configured = false;
    if (!configured) {
        cudaFuncSetAttribute(tucker_main,
                             cudaFuncAttributeMaxDynamicSharedMemorySize,
                             SMEM_BYTES);
        configured = true;
    }

    const int q4 = (n + 3) / 4;
    zero_counts_kernel<<<(NTIME + 255) / 256, 256>>>();
    hist_kernel<<<(q4 + 255) / 256, 256>>>(k_in, n);
    scan_kernel<<<1, 1024>>>();
    scatter_kernel<<<(n + 255) / 256, 256>>>(k_in, i_in, j_in, n);
    tucker_main<<<NUM_CTAS, CTA_THREADS, SMEM_BYTES>>>(U, V, T, C, out);
}

// round 7
// speedup vs baseline: 13.4663x; 1.0104x over previous
#include <cuda_runtime.h>
#include <cstdint>

// Tucker via time-bucketing, round 7:
//   y_n = u_n^T W_{k_n} v_n,   W_k[p,q] = sum_r C[p,q,r] * t_k[r]
// Single-pass slot scatter (fixed CAP per bucket, overflow fallback),
// then persistent main: warp-task = 2 buckets, f32x2 W build, lane=sample.
// Only 2 kernel launches. State (counts/ticket/ovf) cycles across graph
// replays: main zeroes counts after use, scatter resets ticket/ovf.

#define NTIME       5000
#define NTASKS      (NTIME / 2)
#define NUM_CTAS    148
#define CTA_THREADS 384
#define WARPS       (CTA_THREADS / 32)
#define CAP         96

// ---- device scratch (zero-initialized at load) ----
__device__ int g_counts[NTIME];
__device__ int g_slot_idx[NTIME * CAP];
__device__ int g_slot_i[NTIME * CAP];
__device__ int g_slot_j[NTIME * CAP];
__device__ int g_ovf[4096];
__device__ int g_ovf_cnt;
__device__ int g_ticket;

__global__ void scatter_kernel(const int* __restrict__ k_in,
                               const int* __restrict__ i_in,
                               const int* __restrict__ j_in, int n) {
    int t = blockIdx.x * blockDim.x + threadIdx.x;
    if (t == 0) g_ticket = 0;          // consumed only by main (later kernel)
    int base = t * 4;
    if (base + 3 < n) {
        int4 k4 = *(const int4*)(k_in + base);
        int4 i4 = *(const int4*)(i_in + base);
        int4 j4 = *(const int4*)(j_in + base);
        int kk[4] = {k4.x, k4.y, k4.z, k4.w};
        int ii[4] = {i4.x, i4.y, i4.z, i4.w};
        int jj[4] = {j4.x, j4.y, j4.z, j4.w};
        int pos[4];
        #pragma unroll
        for (int s = 0; s < 4; s++) pos[s] = atomicAdd(&g_counts[kk[s]], 1);
        #pragma unroll
        for (int s = 0; s < 4; s++) {
            if (pos[s] < CAP) {
                int sp = kk[s] * CAP + pos[s];
                g_slot_idx[sp] = base + s;
                g_slot_i[sp]   = ii[s];
                g_slot_j[sp]   = jj[s];
            } else {
                int o = atomicAdd(&g_ovf_cnt, 1);
                if (o < 4096) g_ovf[o] = base + s;
            }
        }
    } else {
        for (int x = base; x < n; x++) {
            int k = k_in[x];
            int pos = atomicAdd(&g_counts[k], 1);
            if (pos < CAP) {
                int sp = k * CAP + pos;
                g_slot_idx[sp] = x;
                g_slot_i[sp]   = i_in[x];
                g_slot_j[sp]   = j_in[x];
            } else {
                int o = atomicAdd(&g_ovf_cnt, 1);
                if (o < 4096) g_ovf[o] = x;
            }
        }
    }
}

// ---- packed f32x2 helpers ----
#define PACK2(d, lo, hi) asm("mov.b64 %0, {%1, %2};" : "=l"(d) : "f"(lo), "f"(hi))
#define UNPACK2(lo, hi, s) asm("mov.b64 {%0, %1}, %2;" : "=f"(lo), "=f"(hi) : "l"(s))
#define FMA2(acc, a, b) asm("fma.rn.f32x2 %0, %1, %2, %0;" : "+l"(acc) : "l"(a), "l"(b))
#define LDS64(d, addr) asm volatile("ld.shared.b64 %0, [%1];" : "=l"(d) : "r"(addr))
#define LDSV2U64(d0, d1, addr) \
    asm volatile("ld.shared.v2.u64 {%0, %1}, [%2];" : "=l"(d0), "=l"(d1) : "r"(addr))

__device__ __forceinline__ uint32_t smem_u32(const void* p) {
    uint32_t a;
    asm("{ .reg .u64 t; cvta.to.shared.u64 t, %1; cvt.u32.u64 %0, t; }" : "=r"(a) : "l"(p));
    return a;
}

// ---- main kernel ----
// SMEM bytes:
//   [0, 131072)            C packed: float2(C[2p2][q][r], C[2p2+1][q][r]) at
//                          byte r*4096 + p2*256 + q*8
//   [131072, +WARPS*8K)    per-warp W0 (4KB) + W1 (4KB), row-major [p][q]
#define SM_C_BYTES 131072
#define SMEM_BYTES (SM_C_BYTES + WARPS * 8192)

__device__ __forceinline__ void process_bucket(
    uint32_t Waddr, int b, int cnt,
    const float* __restrict__ U, const float* __restrict__ V,
    float* __restrict__ out, int lane)
{
    const int sbase = b * CAP;
    for (int base = 0; base < cnt; base += 32) {
        const int rem = cnt - base;
        const int sp  = sbase + base + min(lane, rem - 1);
        const int iu  = g_slot_i[sp];
        const int ij  = g_slot_j[sp];
        const int idx = g_slot_idx[sp];

        float ua[32], va[32];
        {
            const float4* up = (const float4*)(U + (size_t)iu * 32);
            const float4* vp = (const float4*)(V + (size_t)ij * 32);
            #pragma unroll
            for (int x = 0; x < 8; x++) {
                float4 t = up[x];
                ua[4*x] = t.x; ua[4*x+1] = t.y; ua[4*x+2] = t.z; ua[4*x+3] = t.w;
            }
            #pragma unroll
            for (int x = 0; x < 8; x++) {
                float4 t = vp[x];
                va[4*x] = t.x; va[4*x+1] = t.y; va[4*x+2] = t.z; va[4*x+3] = t.w;
            }
        }

        unsigned long long a2[16];
        #pragma unroll
        for (int x = 0; x < 16; x++) a2[x] = 0ULL;

        #pragma unroll 8
        for (int p = 0; p < 32; p++) {
            unsigned long long upk;
            PACK2(upk, ua[p], ua[p]);
            const uint32_t row = Waddr + (uint32_t)p * 128u;   // uniform -> broadcast
            #pragma unroll
            for (int q4 = 0; q4 < 8; q4++) {
                unsigned long long c0, c1;
                LDSV2U64(c0, c1, row + q4 * 16u);
                FMA2(a2[2*q4],     upk, c0);
                FMA2(a2[2*q4 + 1], upk, c1);
            }
        }

        unsigned long long acc2 = 0ULL;
        #pragma unroll
        for (int q2 = 0; q2 < 16; q2++) {
            unsigned long long v2;
            PACK2(v2, va[2*q2], va[2*q2+1]);
            FMA2(acc2, a2[q2], v2);
        }
        float ylo, yhi;
        UNPACK2(ylo, yhi, acc2);
        if (lane < rem) out[idx] = ylo + yhi;
    }
}

__global__ void __launch_bounds__(CTA_THREADS, 1)
tucker_main(const int* __restrict__ i_in, const int* __restrict__ j_in,
            const int* __restrict__ k_in,
            const float* __restrict__ U, const float* __restrict__ V,
            const float* __restrict__ T, const float* __restrict__ C,
            float* __restrict__ out)
{
    extern __shared__ float sm[];
    const uint32_t smb = smem_u32(sm);
    const int tid  = threadIdx.x;
    const int wid  = tid >> 5;
    const int lane = tid & 31;

    // stage C: C[p][q][r] -> packed float2 over p-pairs
    for (int idx = tid; idx < 32768; idx += CTA_THREADS) {
        int p = idx >> 10, q = (idx >> 5) & 31, r = idx & 31;
        sm[((r * 16 + (p >> 1)) * 32 + q) * 2 + (p & 1)] = C[idx];
    }
    __syncthreads();

    // overflow slow path (expected count 0) — CTA 0, warp 0, uses smem C
    if (blockIdx.x == 0 && wid == 0) {
        int no = g_ovf_cnt;
        if (no > 4096) no = 4096;
        for (int o = 0; o < no; o++) {
            int idx = g_ovf[o];
            int iu = i_in[idx], ij = j_in[idx], ik = k_in[idx];
            float vq = V[(size_t)ij * 32 + lane];
            float ua[32];
            #pragma unroll
            for (int p = 0; p < 32; p++) ua[p] = U[(size_t)iu * 32 + p];
            float acc = 0.f;
            for (int r = 0; r < 32; r++) {
                float tr = T[(size_t)ik * 32 + r];
                float s = 0.f;
                #pragma unroll
                for (int p2 = 0; p2 < 16; p2++) {
                    float2 c2 = *(const float2*)&sm[((r * 16 + p2) * 32 + lane) * 2];
                    s = fmaf(ua[2*p2],     c2.x, s);
                    s = fmaf(ua[2*p2 + 1], c2.y, s);
                }
                acc = fmaf(tr, s, acc);
            }
            float val = acc * vq;
            #pragma unroll
            for (int off = 16; off > 0; off >>= 1)
                val += __shfl_xor_sync(0xffffffffu, val, off);
            if (lane == 0) out[idx] = val;
        }
        if (lane == 0) g_ovf_cnt = 0;   // reset for next replay
    }

    const uint32_t W0addr = smb + SM_C_BYTES + (uint32_t)wid * 8192u;
    const uint32_t W1addr = W0addr + 4096u;
    float* W0f = (float*)(sm) + (SM_C_BYTES / 4) + wid * 2048;
    float* W1f = W0f + 1024;

    while (true) {
        int task;
        if (lane == 0) task = atomicAdd(&g_ticket, 1);
        task = __shfl_sync(0xffffffffu, task, 0);
        if (task >= NTASKS) break;

        const int b0 = task * 2;
        // read bucket counts, then zero them for the next graph replay
        int cnt0, cnt1;
        if (lane == 0) { cnt0 = g_counts[b0];     g_counts[b0]     = 0; }
        if (lane == 1) { cnt1 = g_counts[b0 + 1]; g_counts[b0 + 1] = 0; }
        cnt0 = __shfl_sync(0xffffffffu, cnt0, 0);
        cnt1 = __shfl_sync(0xffffffffu, cnt1, 1);
        cnt0 = min(cnt0, CAP);
        cnt1 = min(cnt1, CAP);

        const float t0v = T[(size_t)b0 * 32 + lane];
        const float t1v = T[(size_t)(b0 + 1) * 32 + lane];

        // W build, packed over p-pairs
        unsigned long long w0[16], w1[16];
        #pragma unroll
        for (int x = 0; x < 16; x++) { w0[x] = 0ULL; w1[x] = 0ULL; }

        #pragma unroll 4
        for (int r = 0; r < 32; r++) {
            float f0 = __shfl_sync(0xffffffffu, t0v, r);
            float f1 = __shfl_sync(0xffffffffu, t1v, r);
            unsigned long long tr0, tr1;
            PACK2(tr0, f0, f0);
            PACK2(tr1, f1, f1);
            const uint32_t ra = smb + (uint32_t)r * 4096u + (uint32_t)lane * 8u;
            #pragma unroll
            for (int p2 = 0; p2 < 16; p2++) {
                unsigned long long c2;
                LDS64(c2, ra + p2 * 256u);
                FMA2(w0[p2], c2, tr0);
                FMA2(w1[p2], c2, tr1);
            }
        }

        // store W row-major [p][q], lane=q (conflict-free)
        #pragma unroll
        for (int p2 = 0; p2 < 16; p2++) {
            float a, b;
            UNPACK2(a, b, w0[p2]);
            W0f[(2*p2) * 32 + lane]     = a;
            W0f[(2*p2 + 1) * 32 + lane] = b;
            UNPACK2(a, b, w1[p2]);
            W1f[(2*p2) * 32 + lane]     = a;
            W1f[(2*p2 + 1) * 32 + lane] = b;
        }
        __syncwarp();

        if (cnt0 > 0) process_bucket(W0addr, b0,     cnt0, U, V, out, lane);
        if (cnt1 > 0) process_bucket(W1addr, b0 + 1, cnt1, U, V, out, lane);
        __syncwarp();   // W smem reused next task
    }
}

extern "C" void kernel_launch(void* const* d_in, const int* in_sizes, int n_in,
                              void* d_out, int out_size)
{
    const int*   i_in = (const int*)d_in[0];
    const int*   j_in = (const int*)d_in[1];
    const int*   k_in = (const int*)d_in[2];
    const float* U    = (const float*)d_in[3];
    const float* V    = (const float*)d_in[4];
    const float* T    = (const float*)d_in[5];
    const float* C    = (const float*)d_in[6];
    float*       out  = (float*)d_out;

    const int n = in_sizes[0];

    static bool configured = false;
    if (!configured) {
        cudaFuncSetAttribute(tucker_main,
                             cudaFuncAttributeMaxDynamicSharedMemorySize,
                             SMEM_BYTES);
        configured = true;
    }

    const int q4 = (n + 3) / 4;
    scatter_kernel<<<(q4 + 255) / 256, 256>>>(k_in, i_in, j_in, n);
    tucker_main<<<NUM_CTAS, CTA_THREADS, SMEM_BYTES>>>(i_in, j_in, k_in,
                                                       U, V, T, C, out);
}